// round 2
// baseline (speedup 1.0000x reference)
#include <cuda_runtime.h>
#include <math.h>

#define G 2048
#define E 512
#define B 16

// ---------------- device scratch (no allocations allowed) ----------------
__device__ float g_q0[E], g_q1[E], g_k0v[E], g_k1v[E];
__device__ float g_S[4];                      // S[a*2+c] = q_a . k_c
__device__ __align__(16) unsigned g_bits[G];  // bit b = xbin[b, g]
__device__ float g_lr3;
__device__ float g_T1[G * B];                 // masked exp-sums per (g, b)
__device__ float g_T0[G * B];                 // unmasked exp-sums per (g, b)
__device__ float g_u[G];                      // fcCox_w @ fc1_w

__device__ __forceinline__ float lrelu(float x) { return x > 0.f ? x : 0.01f * x; }

// ---------------- kernel 0: binarize datax into bitmasks, zero u ---------
__global__ void prep_kernel(const int* __restrict__ datax,
                            const float* __restrict__ k3) {
    int g = blockIdx.x * blockDim.x + threadIdx.x;
    if (g < G) {
        unsigned bits = 0;
#pragma unroll
        for (int b = 0; b < B; b++)
            bits |= (datax[b * G + g] != 0 ? 1u : 0u) << b;
        g_bits[g] = bits;
        g_u[g] = 0.f;
    }
    if (g == 0) g_lr3 = lrelu(k3[0]);
}

// ---------------- kernel 1: q/k projections of the 2 embedding rows ------
__global__ void qk_kernel(const float* __restrict__ embMat,
                          const float* __restrict__ Wq,
                          const float* __restrict__ Wk) {
    int f = blockIdx.x;           // output feature
    int tid = threadIdx.x;        // 128 threads
    const float* wq = Wq + (size_t)f * E;
    const float* wk = Wk + (size_t)f * E;
    float s0q = 0.f, s1q = 0.f, s0k = 0.f, s1k = 0.f;
    for (int e = tid; e < E; e += 128) {
        float e0 = embMat[e], e1 = embMat[E + e];
        float wqe = wq[e], wke = wk[e];
        s0q += e0 * wqe; s1q += e1 * wqe;
        s0k += e0 * wke; s1k += e1 * wke;
    }
#pragma unroll
    for (int o = 16; o > 0; o >>= 1) {
        s0q += __shfl_down_sync(~0u, s0q, o);
        s1q += __shfl_down_sync(~0u, s1q, o);
        s0k += __shfl_down_sync(~0u, s0k, o);
        s1k += __shfl_down_sync(~0u, s1k, o);
    }
    __shared__ float red[4][4];
    int w = tid >> 5, l = tid & 31;
    if (l == 0) { red[w][0] = s0q; red[w][1] = s1q; red[w][2] = s0k; red[w][3] = s1k; }
    __syncthreads();
    if (tid == 0) {
        float a = 0, b = 0, c = 0, d = 0;
        for (int i = 0; i < 4; i++) { a += red[i][0]; b += red[i][1]; c += red[i][2]; d += red[i][3]; }
        g_q0[f] = a; g_q1[f] = b; g_k0v[f] = c; g_k1v[f] = d;
    }
}

// ---------------- kernel 2: the 2x2 score table S ------------------------
__global__ void s_kernel() {
    int t = threadIdx.x;          // 512 threads
    float q0 = g_q0[t], q1 = g_q1[t], k0 = g_k0v[t], k1 = g_k1v[t];
    float p0 = q0 * k0, p1 = q0 * k1, p2 = q1 * k0, p3 = q1 * k1;
#pragma unroll
    for (int o = 16; o > 0; o >>= 1) {
        p0 += __shfl_down_sync(~0u, p0, o);
        p1 += __shfl_down_sync(~0u, p1, o);
        p2 += __shfl_down_sync(~0u, p2, o);
        p3 += __shfl_down_sync(~0u, p3, o);
    }
    __shared__ float red[16][4];
    int w = t >> 5, l = t & 31;
    if (l == 0) { red[w][0] = p0; red[w][1] = p1; red[w][2] = p2; red[w][3] = p3; }
    __syncthreads();
    if (t == 0) {
        float a = 0, b = 0, c = 0, d = 0;
        for (int i = 0; i < 16; i++) { a += red[i][0]; b += red[i][1]; c += red[i][2]; d += red[i][3]; }
        g_S[0] = a; g_S[1] = b; g_S[2] = c; g_S[3] = d;
    }
}

// ---------------- kernel 3: fused bias + origin write + masked softmax ---
// one block per g-row; each thread owns 8 h values (2 float4) in registers.
// T0 and T1 are accumulated DIRECTLY (no tot - T1 subtraction -> no
// catastrophic cancellation).
__global__ void __launch_bounds__(256, 2)
big_kernel(const float* __restrict__ k1m, const float* __restrict__ k2m,
           const float* __restrict__ spm, const float* __restrict__ cmm,
           const float* __restrict__ padm, float* __restrict__ out) {
    int g = blockIdx.x;
    int tid = threadIdx.x;        // 256
    __shared__ float smax[8];
    __shared__ float sAcc[2 * B];
    __shared__ float sM;
    if (tid < 2 * B) sAcc[tid] = 0.f;

    unsigned gb = g_bits[g];
    float lr3 = g_lr3;
    float s00 = g_S[0], s01 = g_S[1], s10 = g_S[2], s11 = g_S[3];

    size_t rowoff = (size_t)g * G;
    const float4* r1 = (const float4*)(k1m + rowoff);
    const float4* r2 = (const float4*)(k2m + rowoff);
    const float4* rs = (const float4*)(spm + rowoff);
    const float4* rc = (const float4*)(cmm + rowoff);
    const float4* rp = (const float4*)(padm + rowoff);

    float4 bias[2];
    uint4 hb[2];
    float lmax = -3.4e38f;
#pragma unroll
    for (int i = 0; i < 2; i++) {
        int h4 = tid + i * 256;
        float4 v1 = r1[h4], v2 = r2[h4], vs = rs[h4], vc = rc[h4], vp = rp[h4];
        float4 bv;
        bv.x = lrelu(v1.x) * vs.x + lrelu(v2.x) * vc.x + lr3 * vp.x;
        bv.y = lrelu(v1.y) * vs.y + lrelu(v2.y) * vc.y + lr3 * vp.y;
        bv.z = lrelu(v1.z) * vs.z + lrelu(v2.z) * vc.z + lr3 * vp.z;
        bv.w = lrelu(v1.w) * vs.w + lrelu(v2.w) * vc.w + lr3 * vp.w;
        bias[i] = bv;
        hb[i] = ((const uint4*)g_bits)[h4];
        lmax = fmaxf(lmax, fmaxf(fmaxf(bv.x, bv.y), fmaxf(bv.z, bv.w)));
        float* obase = out + 16 + rowoff + (size_t)h4 * 4;
#pragma unroll
        for (int b = 0; b < B; b++) {
            int a = (gb >> b) & 1;
            float a0 = a ? s10 : s00;
            float a1 = a ? s11 : s01;
            float4 o;
            o.x = bv.x + (((hb[i].x >> b) & 1) ? a1 : a0);
            o.y = bv.y + (((hb[i].y >> b) & 1) ? a1 : a0);
            o.z = bv.z + (((hb[i].z >> b) & 1) ? a1 : a0);
            o.w = bv.w + (((hb[i].w >> b) & 1) ? a1 : a0);
            *((float4*)(obase + (size_t)b * ((size_t)G * G))) = o;
        }
    }

    // block max of bias row
#pragma unroll
    for (int o = 16; o > 0; o >>= 1) lmax = fmaxf(lmax, __shfl_xor_sync(~0u, lmax, o));
    if ((tid & 31) == 0) smax[tid >> 5] = lmax;
    __syncthreads();
    if (tid == 0) {
        float m = smax[0];
        for (int i = 1; i < 8; i++) m = fmaxf(m, smax[i]);
        sM = m;
    }
    __syncthreads();
    float M = sM;

    float t1[B], t0[B];
#pragma unroll
    for (int b = 0; b < B; b++) { t1[b] = 0.f; t0[b] = 0.f; }
#pragma unroll
    for (int i = 0; i < 2; i++) {
        float e0 = __expf(bias[i].x - M);
        float e1 = __expf(bias[i].y - M);
        float e2 = __expf(bias[i].z - M);
        float e3 = __expf(bias[i].w - M);
#pragma unroll
        for (int b = 0; b < B; b++) {
            float m0 = ((hb[i].x >> b) & 1) ? e0 : 0.f;
            float m1 = ((hb[i].y >> b) & 1) ? e1 : 0.f;
            float m2 = ((hb[i].z >> b) & 1) ? e2 : 0.f;
            float m3 = ((hb[i].w >> b) & 1) ? e3 : 0.f;
            t1[b] += (m0 + m1) + (m2 + m3);
            t0[b] += ((e0 - m0) + (e1 - m1)) + ((e2 - m2) + (e3 - m3));
        }
    }
#pragma unroll
    for (int o = 16; o > 0; o >>= 1) {
#pragma unroll
        for (int b = 0; b < B; b++) {
            t1[b] += __shfl_down_sync(~0u, t1[b], o);
            t0[b] += __shfl_down_sync(~0u, t0[b], o);
        }
    }
    if ((tid & 31) == 0) {
#pragma unroll
        for (int b = 0; b < B; b++) {
            atomicAdd(&sAcc[b], t1[b]);
            atomicAdd(&sAcc[B + b], t0[b]);
        }
    }
    __syncthreads();
    if (tid < B) g_T1[g * B + tid] = sAcc[tid];
    else if (tid < 2 * B) g_T0[g * B + (tid - B)] = sAcc[tid];
}

// ---------------- kernel 4: u = fcCox_w @ fc1_w (column reduce) ----------
__global__ void u_kernel(const float* __restrict__ fc1w,
                         const float* __restrict__ fcCox) {
    int gg = blockIdx.x * blockDim.x + threadIdx.x;  // 8 blocks x 256
    int f0 = blockIdx.y * 128;
    float acc = 0.f;
#pragma unroll 4
    for (int j = 0; j < 128; j++)
        acc += fcCox[f0 + j] * fc1w[(size_t)(f0 + j) * G + gg];
    atomicAdd(&g_u[gg], acc);
}

// ---------------- kernel 5: combine softmax ratio + fc chain -------------
__global__ void final_kernel(const float* __restrict__ fc1b,
                             const float* __restrict__ fcCox,
                             float* __restrict__ out) {
    int b = blockIdx.x;
    int tid = threadIdx.x;   // 256
    float s00 = g_S[0], s01 = g_S[1], s10 = g_S[2], s11 = g_S[3];
    float m0 = fmaxf(s00, s01), m1 = fmaxf(s10, s11);
    float F00 = __expf(s00 - m0), F01 = __expf(s01 - m0);
    float F10 = __expf(s10 - m1), F11 = __expf(s11 - m1);
    float acc = 0.f;
    for (int g = tid; g < G; g += 256) {
        unsigned A = (g_bits[g] >> b) & 1;
        float T1 = g_T1[g * B + b];
        float T0 = g_T0[g * B + b];
        float f1 = A ? F11 : F01;
        float f0 = A ? F10 : F00;
        float num = f1 * T1;
        float den = f0 * T0 + num;
        float attn = num / den;
        float y = (float)A + attn;
        acc += y * g_u[g] + fc1b[g] * fcCox[g];
    }
#pragma unroll
    for (int o = 16; o > 0; o >>= 1) acc += __shfl_down_sync(~0u, acc, o);
    __shared__ float sr[8];
    if ((tid & 31) == 0) sr[tid >> 5] = acc;
    __syncthreads();
    if (tid == 0) {
        float s = sr[0];
        for (int i = 1; i < 8; i++) s += sr[i];
        out[b] = s;
    }
}

// ---------------- launch ----------------
extern "C" void kernel_launch(void* const* d_in, const int* in_sizes, int n_in,
                              void* d_out, int out_size) {
    const int*   datax  = (const int*)d_in[0];
    const float* embMat = (const float*)d_in[1];
    const float* Wq     = (const float*)d_in[2];
    const float* Wk     = (const float*)d_in[3];
    const float* k1     = (const float*)d_in[4];
    const float* k2     = (const float*)d_in[5];
    const float* k3     = (const float*)d_in[6];
    const float* sp     = (const float*)d_in[7];
    const float* cm     = (const float*)d_in[8];
    const float* pad    = (const float*)d_in[9];
    const float* fc1w   = (const float*)d_in[10];
    const float* fc1b   = (const float*)d_in[11];
    const float* fcCox  = (const float*)d_in[12];
    float* out = (float*)d_out;

    prep_kernel<<<8, 256>>>(datax, k3);
    qk_kernel<<<512, 128>>>(embMat, Wq, Wk);
    s_kernel<<<1, 512>>>();
    big_kernel<<<G, 256>>>(k1, k2, sp, cm, pad, out);
    u_kernel<<<dim3(8, 16), 256>>>(fc1w, fcCox);
    final_kernel<<<B, 256>>>(fc1b, fcCox, out);
}